// round 4
// baseline (speedup 1.0000x reference)
#include <cuda_runtime.h>
#include <math.h>

#define SEQ 512
#define BSZ 128
#define NI  1024
#define NH  1024
#define BK  32

// Persistent state (no allocations allowed)
__device__ float g_hbuf[2][BSZ * NH];
__device__ unsigned g_count = 0;
__device__ unsigned g_gen = 0;

__device__ __forceinline__ void grid_sync(unsigned nblk) {
    __syncthreads();
    if (threadIdx.x == 0) {
        __threadfence();
        unsigned gen = g_gen;
        if (atomicAdd(&g_count, 1u) == nblk - 1u) {
            g_count = 0;
            __threadfence();
            atomicAdd(&g_gen, 1u);
        } else {
            while (*((volatile unsigned*)&g_gen) == gen) { }
            __threadfence();
        }
    }
    __syncthreads();
}

__device__ __forceinline__ float sigmoidf_(float v) {
    return 1.0f / (1.0f + expf(-v));
}

// Packed fp32x2 helpers (Blackwell FFMA2 — only reachable via PTX)
__device__ __forceinline__ unsigned long long dup_f32(float v) {
    unsigned long long r;
    unsigned u = __float_as_uint(v);
    asm("mov.b64 %0, {%1, %1};" : "=l"(r) : "r"(u));
    return r;
}
__device__ __forceinline__ void ffma2(unsigned long long& acc,
                                      unsigned long long a,
                                      unsigned long long b) {
    asm("fma.rn.f32x2 %0, %1, %2, %0;" : "+l"(acc) : "l"(a), "l"(b));
}
__device__ __forceinline__ float2 unpack_f32x2(unsigned long long p) {
    unsigned lo, hi;
    asm("mov.b64 {%0, %1}, %2;" : "=r"(lo), "=r"(hi) : "l"(p));
    return make_float2(__uint_as_float(lo), __uint_as_float(hi));
}

// Persistent kernel. Grid = 128 blocks x 256 threads (all co-resident).
// Block b: all 128 batch rows x 8 h-cols [b*8, b*8+8) x all 4 gates.
// GEMM tile 128(M) x 32(N=8cols*4gates) x K=2048 (x-half then h-half), BK=32.
// Thread (ty,tx): 4 batch rows (ty*4..) x 4 gates of h-col tx; packed-pair
// accumulators over gate pairs (i,f) and (g,o); c register-resident.
__global__ void __launch_bounds__(256, 1)
lstm_persistent_kernel(const float* __restrict__ x,
                       const float* __restrict__ w_ih,
                       const float* __restrict__ w_hh,
                       const float* __restrict__ b_ih,
                       const float* __restrict__ b_hh,
                       float* __restrict__ out)
{
    __shared__ float As[2][BK][132];   // [buf][k][m], padded
    __shared__ float Bs[2][BK][36];    // [buf][k][col*4+gate], padded

    const int tid = threadIdx.x;
    const int tx  = tid & 7;             // h-col within tile (0..7)
    const int ty  = tid >> 3;            // 0..31 -> batch rows ty*4..ty*4+3
    const int nh0 = blockIdx.x * 8;
    const unsigned nblk = gridDim.x;     // 128

    // A loader: thread covers row am, 16 consecutive k (aseg half of BK)
    const int am   = tid >> 1;           // 0..127
    const int aseg = (tid & 1) * 16;     // 0 or 16
    // B loader: thread covers colgate bcg, 4 consecutive k
    const int bcg  = tid & 31;           // dest index col*4+gate
    const int bkq  = tid >> 5;           // 0..7 -> k = bkq*4..bkq*4+3
    const int bgrow = (bcg & 3) * NH + nh0 + (bcg >> 2);   // weight row

    const int hcol = nh0 + tx;
    float bc[4];
#pragma unroll
    for (int g = 0; g < 4; g++)
        bc[g] = b_ih[g * NH + hcol] + b_hh[g * NH + hcol];

    float c[4] = {0.f, 0.f, 0.f, 0.f};

    float4 rA[4];
    float4 rB;

    // Prefetch step 0, tile 0 (x-half)
    {
        const float* ab = x + (size_t)am * NI + aseg;
        rA[0] = *(const float4*)(ab + 0);
        rA[1] = *(const float4*)(ab + 4);
        rA[2] = *(const float4*)(ab + 8);
        rA[3] = *(const float4*)(ab + 12);
        rB    = *(const float4*)(w_ih + (size_t)bgrow * NI + bkq * 4);
    }

    for (int s = 0; s < SEQ; s++) {
        const float* xs    = x + (size_t)s * BSZ * NI;
        const float* hprev = g_hbuf[s & 1];
        const int ktEnd = (s == 0) ? 32 : 64;   // h0 == 0: skip recurrent half

        unsigned long long acc[4][2];
#pragma unroll
        for (int i = 0; i < 4; i++) { acc[i][0] = 0ull; acc[i][1] = 0ull; }

        for (int kt = 0; kt < ktEnd; kt++) {
            const int buf = kt & 1;

            // Store prefetched tile to SMEM
#pragma unroll
            for (int q = 0; q < 4; q++) {
                As[buf][aseg + q * 4 + 0][am] = rA[q].x;
                As[buf][aseg + q * 4 + 1][am] = rA[q].y;
                As[buf][aseg + q * 4 + 2][am] = rA[q].z;
                As[buf][aseg + q * 4 + 3][am] = rA[q].w;
            }
            Bs[buf][bkq * 4 + 0][bcg] = rB.x;
            Bs[buf][bkq * 4 + 1][bcg] = rB.y;
            Bs[buf][bkq * 4 + 2][bcg] = rB.z;
            Bs[buf][bkq * 4 + 3][bcg] = rB.w;
            __syncthreads();

            // Prefetch next tile (hidden behind compute)
            if (kt + 1 < ktEnd) {
                const int nk = kt + 1;
                if (nk < 32) {
                    const float* ab = xs + (size_t)am * NI + nk * BK + aseg;
                    rA[0] = *(const float4*)(ab + 0);
                    rA[1] = *(const float4*)(ab + 4);
                    rA[2] = *(const float4*)(ab + 8);
                    rA[3] = *(const float4*)(ab + 12);
                    rB = *(const float4*)(w_ih + (size_t)bgrow * NI + nk * BK + bkq * 4);
                } else {
                    const int ko = (nk - 32) * BK;
                    const float* ab = hprev + (size_t)am * NH + ko + aseg;
                    // h written by other SMs: bypass L1
                    rA[0] = __ldcg((const float4*)(ab + 0));
                    rA[1] = __ldcg((const float4*)(ab + 4));
                    rA[2] = __ldcg((const float4*)(ab + 8));
                    rA[3] = __ldcg((const float4*)(ab + 12));
                    rB = *(const float4*)(w_hh + (size_t)bgrow * NH + ko + bkq * 4);
                }
            } else if (s + 1 < SEQ) {
                // First tile of next step is x-half: prefetch across the grid sync
                const float* ab = xs + (size_t)BSZ * NI + (size_t)am * NI + aseg;
                rA[0] = *(const float4*)(ab + 0);
                rA[1] = *(const float4*)(ab + 4);
                rA[2] = *(const float4*)(ab + 8);
                rA[3] = *(const float4*)(ab + 12);
                rB = *(const float4*)(w_ih + (size_t)bgrow * NI + bkq * 4);
            }

            // Compute on current buffer: 32 k-iters x 8 FFMA2
#pragma unroll
            for (int k = 0; k < BK; k++) {
                float4 a = *(const float4*)&As[buf][k][ty * 4];
                unsigned long long bp0 = *(const unsigned long long*)&Bs[buf][k][tx * 4];
                unsigned long long bp1 = *(const unsigned long long*)&Bs[buf][k][tx * 4 + 2];
                unsigned long long a0 = dup_f32(a.x);
                unsigned long long a1 = dup_f32(a.y);
                unsigned long long a2 = dup_f32(a.z);
                unsigned long long a3 = dup_f32(a.w);
                ffma2(acc[0][0], a0, bp0); ffma2(acc[0][1], a0, bp1);
                ffma2(acc[1][0], a1, bp0); ffma2(acc[1][1], a1, bp1);
                ffma2(acc[2][0], a2, bp0); ffma2(acc[2][1], a2, bp1);
                ffma2(acc[3][0], a3, bp0); ffma2(acc[3][1], a3, bp1);
            }
        }

        // Fused LSTM cell update (register-local)
        float* hnext = g_hbuf[(s + 1) & 1];
#pragma unroll
        for (int i = 0; i < 4; i++) {
            const int m = ty * 4 + i;
            float2 vif = unpack_f32x2(acc[i][0]);   // (i, f) gates
            float2 vgo = unpack_f32x2(acc[i][1]);   // (g, o) gates
            const float ig = sigmoidf_(vif.x + bc[0]);
            const float fg = sigmoidf_(vif.y + bc[1]);
            const float gg = tanhf(vgo.x + bc[2]);
            const float og = sigmoidf_(vgo.y + bc[3]);
            const float cv = fg * c[i] + ig * gg;
            c[i] = cv;
            const float hv = og * tanhf(cv);
            hnext[(size_t)m * NH + hcol] = hv;
            out[((size_t)s * BSZ + m) * NH + hcol] = hv;
            if (s == SEQ - 1) {
                out[((size_t)SEQ * BSZ + m) * NH + hcol] = hv;               // hN
                out[((size_t)(SEQ * BSZ + BSZ) + m) * NH + hcol] = cv;       // cN
            }
        }

        grid_sync(nblk);   // h(s+1) visible chip-wide before next step reads it
    }
}

extern "C" void kernel_launch(void* const* d_in, const int* in_sizes, int n_in,
                              void* d_out, int out_size)
{
    const float* x    = (const float*)d_in[0];
    const float* w_ih = (const float*)d_in[1];
    const float* w_hh = (const float*)d_in[2];
    const float* b_ih = (const float*)d_in[3];
    const float* b_hh = (const float*)d_in[4];
    float* out = (float*)d_out;

    lstm_persistent_kernel<<<128, 256>>>(x, w_ih, w_hh, b_ih, b_hh, out);
}

// round 5
// speedup vs baseline: 1.0007x; 1.0007x over previous
#include <cuda_runtime.h>
#include <math.h>

#define SEQ 512
#define BSZ 128
#define NI  1024
#define NH  1024
#define BK  32

// Persistent state (no allocations allowed)
__device__ float g_hbuf[2][BSZ * NH];
__device__ unsigned g_count = 0;
__device__ unsigned g_gen = 0;

__device__ __forceinline__ void grid_sync(unsigned nblk) {
    __syncthreads();
    if (threadIdx.x == 0) {
        __threadfence();
        unsigned gen = g_gen;
        if (atomicAdd(&g_count, 1u) == nblk - 1u) {
            g_count = 0;
            __threadfence();
            atomicAdd(&g_gen, 1u);
        } else {
            while (*((volatile unsigned*)&g_gen) == gen) { }
            __threadfence();
        }
    }
    __syncthreads();
}

__device__ __forceinline__ float sigmoidf_(float v) {
    return 1.0f / (1.0f + expf(-v));
}

// Packed fp32x2 helpers (Blackwell FFMA2 — only reachable via PTX)
__device__ __forceinline__ unsigned long long dup_f32(float v) {
    unsigned long long r;
    unsigned u = __float_as_uint(v);
    asm("mov.b64 %0, {%1, %1};" : "=l"(r) : "r"(u));
    return r;
}
__device__ __forceinline__ void ffma2(unsigned long long& acc,
                                      unsigned long long a,
                                      unsigned long long b) {
    asm("fma.rn.f32x2 %0, %1, %2, %0;" : "+l"(acc) : "l"(a), "l"(b));
}
__device__ __forceinline__ float2 unpack_f32x2(unsigned long long p) {
    unsigned lo, hi;
    asm("mov.b64 {%0, %1}, %2;" : "=r"(lo), "=r"(hi) : "l"(p));
    return make_float2(__uint_as_float(lo), __uint_as_float(hi));
}

// Persistent kernel. Grid = 128 blocks x 256 threads (all co-resident).
// Block b: all 128 batch rows x 8 h-cols [b*8, b*8+8) x all 4 gates.
// GEMM tile 128(M) x 32(N=8cols*4gates) x K=2048 (x-half then h-half), BK=32.
// Thread (ty,tx): 4 batch rows (ty*4..) x 4 gates of h-col tx; packed-pair
// accumulators over gate pairs (i,f) and (g,o); c register-resident.
__global__ void __launch_bounds__(256, 1)
lstm_persistent_kernel(const float* __restrict__ x,
                       const float* __restrict__ w_ih,
                       const float* __restrict__ w_hh,
                       const float* __restrict__ b_ih,
                       const float* __restrict__ b_hh,
                       float* __restrict__ out)
{
    __shared__ float As[2][BK][132];   // [buf][k][m], padded
    __shared__ float Bs[2][BK][36];    // [buf][k][col*4+gate], padded

    const int tid = threadIdx.x;
    const int tx  = tid & 7;             // h-col within tile (0..7)
    const int ty  = tid >> 3;            // 0..31 -> batch rows ty*4..ty*4+3
    const int nh0 = blockIdx.x * 8;
    const unsigned nblk = gridDim.x;     // 128

    // A loader: thread covers row am, 16 consecutive k (aseg half of BK)
    const int am   = tid >> 1;           // 0..127
    const int aseg = (tid & 1) * 16;     // 0 or 16
    // B loader: thread covers colgate bcg, 4 consecutive k
    const int bcg  = tid & 31;           // dest index col*4+gate
    const int bkq  = tid >> 5;           // 0..7 -> k = bkq*4..bkq*4+3
    const int bgrow = (bcg & 3) * NH + nh0 + (bcg >> 2);   // weight row

    const int hcol = nh0 + tx;
    float bc[4];
#pragma unroll
    for (int g = 0; g < 4; g++)
        bc[g] = b_ih[g * NH + hcol] + b_hh[g * NH + hcol];

    float c[4] = {0.f, 0.f, 0.f, 0.f};

    float4 rA[4];
    float4 rB;

    // Prefetch step 0, tile 0 (x-half)
    {
        const float* ab = x + (size_t)am * NI + aseg;
        rA[0] = *(const float4*)(ab + 0);
        rA[1] = *(const float4*)(ab + 4);
        rA[2] = *(const float4*)(ab + 8);
        rA[3] = *(const float4*)(ab + 12);
        rB    = *(const float4*)(w_ih + (size_t)bgrow * NI + bkq * 4);
    }

    for (int s = 0; s < SEQ; s++) {
        const float* xs    = x + (size_t)s * BSZ * NI;
        const float* hprev = g_hbuf[s & 1];
        const int ktEnd = (s == 0) ? 32 : 64;   // h0 == 0: skip recurrent half

        unsigned long long acc[4][2];
#pragma unroll
        for (int i = 0; i < 4; i++) { acc[i][0] = 0ull; acc[i][1] = 0ull; }

        for (int kt = 0; kt < ktEnd; kt++) {
            const int buf = kt & 1;

            // Store prefetched tile to SMEM
#pragma unroll
            for (int q = 0; q < 4; q++) {
                As[buf][aseg + q * 4 + 0][am] = rA[q].x;
                As[buf][aseg + q * 4 + 1][am] = rA[q].y;
                As[buf][aseg + q * 4 + 2][am] = rA[q].z;
                As[buf][aseg + q * 4 + 3][am] = rA[q].w;
            }
            Bs[buf][bkq * 4 + 0][bcg] = rB.x;
            Bs[buf][bkq * 4 + 1][bcg] = rB.y;
            Bs[buf][bkq * 4 + 2][bcg] = rB.z;
            Bs[buf][bkq * 4 + 3][bcg] = rB.w;
            __syncthreads();

            // Prefetch next tile (hidden behind compute)
            if (kt + 1 < ktEnd) {
                const int nk = kt + 1;
                if (nk < 32) {
                    const float* ab = xs + (size_t)am * NI + nk * BK + aseg;
                    rA[0] = *(const float4*)(ab + 0);
                    rA[1] = *(const float4*)(ab + 4);
                    rA[2] = *(const float4*)(ab + 8);
                    rA[3] = *(const float4*)(ab + 12);
                    rB = *(const float4*)(w_ih + (size_t)bgrow * NI + nk * BK + bkq * 4);
                } else {
                    const int ko = (nk - 32) * BK;
                    const float* ab = hprev + (size_t)am * NH + ko + aseg;
                    // h written by other SMs: bypass L1
                    rA[0] = __ldcg((const float4*)(ab + 0));
                    rA[1] = __ldcg((const float4*)(ab + 4));
                    rA[2] = __ldcg((const float4*)(ab + 8));
                    rA[3] = __ldcg((const float4*)(ab + 12));
                    rB = *(const float4*)(w_hh + (size_t)bgrow * NH + ko + bkq * 4);
                }
            } else if (s + 1 < SEQ) {
                // First tile of next step is x-half: prefetch across the grid sync
                const float* ab = xs + (size_t)BSZ * NI + (size_t)am * NI + aseg;
                rA[0] = *(const float4*)(ab + 0);
                rA[1] = *(const float4*)(ab + 4);
                rA[2] = *(const float4*)(ab + 8);
                rA[3] = *(const float4*)(ab + 12);
                rB = *(const float4*)(w_ih + (size_t)bgrow * NI + bkq * 4);
            }

            // Compute on current buffer: 32 k-iters x 8 FFMA2
#pragma unroll
            for (int k = 0; k < BK; k++) {
                float4 a = *(const float4*)&As[buf][k][ty * 4];
                unsigned long long bp0 = *(const unsigned long long*)&Bs[buf][k][tx * 4];
                unsigned long long bp1 = *(const unsigned long long*)&Bs[buf][k][tx * 4 + 2];
                unsigned long long a0 = dup_f32(a.x);
                unsigned long long a1 = dup_f32(a.y);
                unsigned long long a2 = dup_f32(a.z);
                unsigned long long a3 = dup_f32(a.w);
                ffma2(acc[0][0], a0, bp0); ffma2(acc[0][1], a0, bp1);
                ffma2(acc[1][0], a1, bp0); ffma2(acc[1][1], a1, bp1);
                ffma2(acc[2][0], a2, bp0); ffma2(acc[2][1], a2, bp1);
                ffma2(acc[3][0], a3, bp0); ffma2(acc[3][1], a3, bp1);
            }
        }

        // Fused LSTM cell update (register-local)
        float* hnext = g_hbuf[(s + 1) & 1];
#pragma unroll
        for (int i = 0; i < 4; i++) {
            const int m = ty * 4 + i;
            float2 vif = unpack_f32x2(acc[i][0]);   // (i, f) gates
            float2 vgo = unpack_f32x2(acc[i][1]);   // (g, o) gates
            const float ig = sigmoidf_(vif.x + bc[0]);
            const float fg = sigmoidf_(vif.y + bc[1]);
            const float gg = tanhf(vgo.x + bc[2]);
            const float og = sigmoidf_(vgo.y + bc[3]);
            const float cv = fg * c[i] + ig * gg;
            c[i] = cv;
            const float hv = og * tanhf(cv);
            hnext[(size_t)m * NH + hcol] = hv;
            out[((size_t)s * BSZ + m) * NH + hcol] = hv;
            if (s == SEQ - 1) {
                out[((size_t)SEQ * BSZ + m) * NH + hcol] = hv;               // hN
                out[((size_t)(SEQ * BSZ + BSZ) + m) * NH + hcol] = cv;       // cN
            }
        }

        grid_sync(nblk);   // h(s+1) visible chip-wide before next step reads it
    }
}

extern "C" void kernel_launch(void* const* d_in, const int* in_sizes, int n_in,
                              void* d_out, int out_size)
{
    const float* x    = (const float*)d_in[0];
    const float* w_ih = (const float*)d_in[1];
    const float* w_hh = (const float*)d_in[2];
    const float* b_ih = (const float*)d_in[3];
    const float* b_hh = (const float*)d_in[4];
    float* out = (float*)d_out;

    lstm_persistent_kernel<<<128, 256>>>(x, w_ih, w_hh, b_ih, b_hh, out);
}

// round 9
// speedup vs baseline: 3.1736x; 3.1715x over previous
#include <cuda_runtime.h>
#include <cuda_bf16.h>
#include <math.h>
#include <stdint.h>

#define SEQ 512
#define NBLK 128

// ---- device globals (no allocations allowed) ----
// Pre-packed weight fragments: [bid][ks(32)][mhalf(2)][mt4(4)][prod(2)][lane(32)] = 32MB
__device__ uint4 g_w[NBLK][32][2][4][2][32];
__device__ float g_part[4 * 32 * 128 * 128];   // [kg*32+mt][n*128+m] 8MB
__device__ float g_h[128 * 1024];
__device__ unsigned g_count = 0, g_gen = 0;

__device__ __forceinline__ void grid_sync() {
    __syncthreads();
    if (threadIdx.x == 0) {
        __threadfence();
        unsigned gen = g_gen;
        if (atomicAdd(&g_count, 1u) == NBLK - 1u) {
            g_count = 0; __threadfence(); atomicAdd(&g_gen, 1u);
        } else {
            while (*((volatile unsigned*)&g_gen) == gen) { }
            __threadfence();
        }
    }
    __syncthreads();
}

__device__ __forceinline__ float sigmoidf_(float v) { return 1.0f / (1.0f + expf(-v)); }

// fp32 pair -> bf16x2 hi + bf16x2 lo (3-product split halves)
__device__ __forceinline__ void hilo(float2 f, uint32_t& h, uint32_t& l) {
    __nv_bfloat162 hb = __floats2bfloat162_rn(f.x, f.y);
    float2 hf = __bfloat1622float2(hb);
    __nv_bfloat162 lb = __floats2bfloat162_rn(f.x - hf.x, f.y - hf.y);
    h = *(uint32_t*)&hb;
    l = *(uint32_t*)&lb;
}

#define MMA(c, a, b0, b1) \
    asm volatile("mma.sync.aligned.m16n8k16.row.col.f32.bf16.bf16.f32 " \
        "{%0,%1,%2,%3},{%4,%5,%6,%7},{%8,%9},{%0,%1,%2,%3};" \
        : "+f"((c)[0]), "+f"((c)[1]), "+f"((c)[2]), "+f"((c)[3]) \
        : "r"((a).x), "r"((a).y), "r"((a).z), "r"((a).w), "r"(b0), "r"(b1))

// Persistent kernel: block bid = (mt = bid>>2 in 0..31, kg = bid&3).
// Gate rows [mt*128, +128) x all 128 batch, K-slice [kg*512, +512) of fused
// K=2048 (x||h). Warp w: m-half wm = w>>2, n-quarter wn = w&3 (32 batch).
__global__ void __launch_bounds__(256, 1)
lstm_mma_kernel(const float* __restrict__ x, const float* __restrict__ w_ih,
                const float* __restrict__ w_hh, const float* __restrict__ b_ih,
                const float* __restrict__ b_hh, float* __restrict__ out)
{
    const int tid  = threadIdx.x;
    const int lane = tid & 31, wid = tid >> 5;
    const int bid  = blockIdx.x, mt = bid >> 2, kg = bid & 3;
    const int wm   = wid >> 2, wn = wid & 3;
    const int gr   = lane >> 2, gc = (lane & 3) * 2;

    // zero h (replays must be deterministic)
    *(float4*)&g_h[bid * 1024 + tid * 4] = make_float4(0.f, 0.f, 0.f, 0.f);

    // ---- prologue: pack this block's W slice into per-lane fragments ----
    {
        const float* Wsrc = (kg < 2) ? (w_ih + kg * 512) : (w_hh + (kg - 2) * 512);
        for (int grp = wid; grp < 256; grp += 8) {
            const int ks = grp >> 3, mh = (grp >> 2) & 1, m4 = grp & 3;
            const int row = mt * 128 + mh * 64 + m4 * 16 + gr;
            const int col = ks * 16 + gc;
            const float* p0 = Wsrc + (size_t)row * 1024 + col;
            const float* p1 = Wsrc + (size_t)(row + 8) * 1024 + col;
            float2 f00 = *(const float2*)p0;         // (gr,   gc)
            float2 f10 = *(const float2*)p1;         // (gr+8, gc)
            float2 f01 = *(const float2*)(p0 + 8);   // (gr,   gc+8)
            float2 f11 = *(const float2*)(p1 + 8);   // (gr+8, gc+8)
            uint32_t h0, l0, h1, l1, h2, l2, h3, l3;
            hilo(f00, h0, l0); hilo(f10, h1, l1);
            hilo(f01, h2, l2); hilo(f11, h3, l3);
            g_w[bid][ks][mh][m4][0][lane] = make_uint4(h0, h1, h2, h3);
            g_w[bid][ks][mh][m4][1][lane] = make_uint4(l0, l1, l2, l3);
        }
    }

    // pointwise constants (each thread owns 4 (b,h) elements)
    const int gthr = bid * 256 + tid;
    float bcr[4][4], creg[4] = {0.f, 0.f, 0.f, 0.f};
#pragma unroll
    for (int e = 0; e < 4; e++) {
        const int hc = (e * 32768 + gthr) & 1023;
#pragma unroll
        for (int g4 = 0; g4 < 4; g4++)
            bcr[e][g4] = b_ih[g4 * 1024 + hc] + b_hh[g4 * 1024 + hc];
    }
    grid_sync();   // g_w + zeroed g_h visible chip-wide

    const int  nB   = wn * 32 + (lane >> 2);   // B-fragment batch row (+nt*8)
    const int  kO   = (lane & 3) * 2;          // B-fragment k offset
    const int  aoff = (kg & 1) * 512;          // col base within x or h
    const bool useh = (kg >= 2);
    float* pbase = g_part + ((size_t)(kg * 32 + mt) << 14);

    for (int s = 0; s < SEQ; s++) {
        const float* act = useh ? (g_h + aoff)
                                : (x + (size_t)s * 131072 + aoff);
        float acc[4][4][4];
#pragma unroll
        for (int m = 0; m < 4; m++)
#pragma unroll
            for (int nt = 0; nt < 4; nt++)
#pragma unroll
                for (int q = 0; q < 4; q++) acc[m][nt][q] = 0.f;

#pragma unroll 2
        for (int ks = 0; ks < 32; ks++) {
            uint4 Ah[4], Al[4];
#pragma unroll
            for (int m = 0; m < 4; m++) {
                Ah[m] = g_w[bid][ks][wm][m][0][lane];
                Al[m] = g_w[bid][ks][wm][m][1][lane];
            }
            const int kbase = ks * 16 + kO;
#pragma unroll
            for (int nt = 0; nt < 4; nt++) {
                const float* ap = act + (size_t)(nB + nt * 8) * 1024 + kbase;
                float2 p0, p1;
                if (useh) { p0 = __ldcg((const float2*)ap); p1 = __ldcg((const float2*)(ap + 8)); }
                else      { p0 = __ldg ((const float2*)ap); p1 = __ldg ((const float2*)(ap + 8)); }
                uint32_t bh0, bl0, bh1, bl1;
                hilo(p0, bh0, bl0);
                hilo(p1, bh1, bl1);
#pragma unroll
                for (int m = 0; m < 4; m++) {
                    MMA(acc[m][nt], Ah[m], bh0, bh1);   // w_hi * a_hi
                    MMA(acc[m][nt], Ah[m], bl0, bl1);   // w_hi * a_lo
                    MMA(acc[m][nt], Al[m], bh0, bh1);   // w_lo * a_hi
                }
            }
        }

        // write partials, layout [n][m] (pointwise reads coalesced)
#pragma unroll
        for (int m = 0; m < 4; m++) {
#pragma unroll
            for (int nt = 0; nt < 4; nt++) {
                const int mrow = wm * 64 + m * 16 + gr;
                const int ncol = wn * 32 + nt * 8 + 2 * (lane & 3);
                pbase[(size_t)ncol * 128 + mrow]           = acc[m][nt][0];
                pbase[(size_t)(ncol + 1) * 128 + mrow]     = acc[m][nt][1];
                pbase[(size_t)ncol * 128 + mrow + 8]       = acc[m][nt][2];
                pbase[(size_t)(ncol + 1) * 128 + mrow + 8] = acc[m][nt][3];
            }
        }
        grid_sync();   // all partials visible

        // fused pointwise (c register-resident)
#pragma unroll
        for (int e = 0; e < 4; e++) {
            const int idx = e * 32768 + gthr, bb = idx >> 10, hc = idx & 1023;
            float gv[4];
#pragma unroll
            for (int g4 = 0; g4 < 4; g4++) {
                const int grow = g4 * 1024 + hc;
                const int mtg = grow >> 7, mr = grow & 127;
                float sum = bcr[e][g4];
#pragma unroll
                for (int kgi = 0; kgi < 4; kgi++)
                    sum += __ldcg(&g_part[((size_t)(kgi * 32 + mtg) << 14) + (size_t)bb * 128 + mr]);
                gv[g4] = sum;
            }
            const float ig = sigmoidf_(gv[0]), fg = sigmoidf_(gv[1]);
            const float gg = tanhf(gv[2]),     og = sigmoidf_(gv[3]);
            const float cv = fg * creg[e] + ig * gg;
            creg[e] = cv;
            const float hv = og * tanhf(cv);
            g_h[idx] = hv;
            out[(size_t)s * 131072 + idx] = hv;
            if (s == SEQ - 1) {
                out[(size_t)512 * 131072 + idx] = hv;            // hN
                out[(size_t)512 * 131072 + 131072 + idx] = cv;   // cN
            }
        }
        grid_sync();   // h(s+1) visible before next step's B loads
    }
}

extern "C" void kernel_launch(void* const* d_in, const int* in_sizes, int n_in,
                              void* d_out, int out_size)
{
    lstm_mma_kernel<<<NBLK, 256>>>((const float*)d_in[0], (const float*)d_in[1],
                                   (const float*)d_in[2], (const float*)d_in[3],
                                   (const float*)d_in[4], (float*)d_out);
}

// round 10
// speedup vs baseline: 3.4891x; 1.0994x over previous
#include <cuda_runtime.h>
#include <cuda_bf16.h>
#include <math.h>
#include <stdint.h>

#define SEQ 512
#define NBLK 128

// ---- device globals (no allocations allowed) ----
// Pre-packed weight fragments: [bid][ks(32)][mt8(8)][prod(2)][lane(32)] = 32MB
__device__ uint4 g_w[NBLK][32][8][2][32];
__device__ float g_part[4 * 32 * 128 * 128];   // [kg*32+mt][n*128+m] 8MB
__device__ float g_h[128 * 1024];
__device__ unsigned g_count = 0, g_gen = 0;

__device__ __forceinline__ void grid_sync() {
    __syncthreads();
    if (threadIdx.x == 0) {
        __threadfence();
        unsigned gen = g_gen;
        if (atomicAdd(&g_count, 1u) == NBLK - 1u) {
            g_count = 0; __threadfence(); atomicAdd(&g_gen, 1u);
        } else {
            while (*((volatile unsigned*)&g_gen) == gen) { }
            __threadfence();
        }
    }
    __syncthreads();
}

__device__ __forceinline__ float sigmoidf_(float v) { return 1.0f / (1.0f + expf(-v)); }

// fp32 pair -> bf16x2 hi + bf16x2 lo (3-product split halves)
__device__ __forceinline__ void hilo(float2 f, uint32_t& h, uint32_t& l) {
    __nv_bfloat162 hb = __floats2bfloat162_rn(f.x, f.y);
    float2 hf = __bfloat1622float2(hb);
    __nv_bfloat162 lb = __floats2bfloat162_rn(f.x - hf.x, f.y - hf.y);
    h = *(uint32_t*)&hb;
    l = *(uint32_t*)&lb;
}

#define MMA(c, a, b0, b1) \
    asm volatile("mma.sync.aligned.m16n8k16.row.col.f32.bf16.bf16.f32 " \
        "{%0,%1,%2,%3},{%4,%5,%6,%7},{%8,%9},{%0,%1,%2,%3};" \
        : "+f"((c)[0]), "+f"((c)[1]), "+f"((c)[2]), "+f"((c)[3]) \
        : "r"((a).x), "r"((a).y), "r"((a).z), "r"((a).w), "r"(b0), "r"(b1))

// Persistent kernel: 128 blocks x 512 threads (16 warps; occ 25%).
// Block bid = (mt = bid>>2, kg = bid&3): gate rows [mt*128,+128) x 128 batch,
// K-slice [kg*512,+512) of fused K=2048 (x||h).
// Warp: wm = wid>>3 (m-half, 64 rows), wn = wid&7 (16 batch cols).
__global__ void __launch_bounds__(512, 1)
lstm_mma_kernel(const float* __restrict__ x, const float* __restrict__ w_ih,
                const float* __restrict__ w_hh, const float* __restrict__ b_ih,
                const float* __restrict__ b_hh, float* __restrict__ out)
{
    const int tid  = threadIdx.x;
    const int lane = tid & 31, wid = tid >> 5;
    const int bid  = blockIdx.x, mt = bid >> 2, kg = bid & 3;
    const int wm   = wid >> 3, wn = wid & 7;
    const int gr   = lane >> 2, gc = (lane & 3) * 2;

    // zero h (replays must be deterministic)
    *(float2*)&g_h[bid * 1024 + tid * 2] = make_float2(0.f, 0.f);

    // ---- prologue: pack this block's W slice into per-lane fragments ----
    {
        const float* Wsrc = (kg < 2) ? (w_ih + kg * 512) : (w_hh + (kg - 2) * 512);
        for (int grp = wid; grp < 256; grp += 16) {
            const int ks = grp >> 3, mt8 = grp & 7;
            const int row = mt * 128 + mt8 * 16 + gr;
            const int col = ks * 16 + gc;
            const float* p0 = Wsrc + (size_t)row * 1024 + col;
            const float* p1 = Wsrc + (size_t)(row + 8) * 1024 + col;
            float2 f00 = *(const float2*)p0;         // (gr,   gc)
            float2 f10 = *(const float2*)p1;         // (gr+8, gc)
            float2 f01 = *(const float2*)(p0 + 8);   // (gr,   gc+8)
            float2 f11 = *(const float2*)(p1 + 8);   // (gr+8, gc+8)
            uint32_t h0, l0, h1, l1, h2, l2, h3, l3;
            hilo(f00, h0, l0); hilo(f10, h1, l1);
            hilo(f01, h2, l2); hilo(f11, h3, l3);
            g_w[bid][ks][mt8][0][lane] = make_uint4(h0, h1, h2, h3);
            g_w[bid][ks][mt8][1][lane] = make_uint4(l0, l1, l2, l3);
        }
    }

    // pointwise constants (each thread owns 2 (b,h) elements)
    const int gthr = bid * 512 + tid;
    float bcr[2][4], creg[2] = {0.f, 0.f};
#pragma unroll
    for (int e = 0; e < 2; e++) {
        const int hc = (e * 65536 + gthr) & 1023;
#pragma unroll
        for (int g4 = 0; g4 < 4; g4++)
            bcr[e][g4] = b_ih[g4 * 1024 + hc] + b_hh[g4 * 1024 + hc];
    }
    grid_sync();   // g_w + zeroed g_h visible chip-wide

    const int  nB   = wn * 16 + gr;            // B-fragment batch row (+nt*8)
    const int  kO   = (lane & 3) * 2;          // B-fragment k offset
    const int  aoff = (kg & 1) * 512;          // col base within x or h
    const bool useh = (kg >= 2);
    float* pbase = g_part + ((size_t)(kg * 32 + mt) << 14);

    for (int s = 0; s < SEQ; s++) {
        const float* act = useh ? (g_h + aoff)
                                : (x + (size_t)s * 131072 + aoff);
        float acc[4][2][4];
#pragma unroll
        for (int m = 0; m < 4; m++)
#pragma unroll
            for (int nt = 0; nt < 2; nt++)
#pragma unroll
                for (int q = 0; q < 4; q++) acc[m][nt][q] = 0.f;

        // preload ks=0 activation pairs
        float2 p0[2], p1[2];
#pragma unroll
        for (int nt = 0; nt < 2; nt++) {
            const float* ap = act + (size_t)(nB + nt * 8) * 1024 + kO;
            if (useh) { p0[nt] = __ldcg((const float2*)ap); p1[nt] = __ldcg((const float2*)(ap + 8)); }
            else      { p0[nt] = __ldg ((const float2*)ap); p1[nt] = __ldg ((const float2*)(ap + 8)); }
        }

#pragma unroll 2
        for (int ks = 0; ks < 32; ks++) {
            // convert current B pairs to hi/lo bf16 fragments
            uint32_t bh0[2], bl0[2], bh1[2], bl1[2];
#pragma unroll
            for (int nt = 0; nt < 2; nt++) {
                hilo(p0[nt], bh0[nt], bl0[nt]);
                hilo(p1[nt], bh1[nt], bl1[nt]);
            }
            // prefetch next ks (overlaps with MMAs below)
            if (ks < 31) {
                const int kbase = (ks + 1) * 16 + kO;
#pragma unroll
                for (int nt = 0; nt < 2; nt++) {
                    const float* ap = act + (size_t)(nB + nt * 8) * 1024 + kbase;
                    if (useh) { p0[nt] = __ldcg((const float2*)ap); p1[nt] = __ldcg((const float2*)(ap + 8)); }
                    else      { p0[nt] = __ldg ((const float2*)ap); p1[nt] = __ldg ((const float2*)(ap + 8)); }
                }
            }
            // A fragments just-in-time (L1 hits), 6 MMAs per m16 tile
#pragma unroll
            for (int m = 0; m < 4; m++) {
                uint4 Ah = g_w[bid][ks][wm * 4 + m][0][lane];
                uint4 Al = g_w[bid][ks][wm * 4 + m][1][lane];
#pragma unroll
                for (int nt = 0; nt < 2; nt++) {
                    MMA(acc[m][nt], Ah, bh0[nt], bh1[nt]);   // w_hi * a_hi
                    MMA(acc[m][nt], Ah, bl0[nt], bl1[nt]);   // w_hi * a_lo
                    MMA(acc[m][nt], Al, bh0[nt], bh1[nt]);   // w_lo * a_hi
                }
            }
        }

        // write partials, layout [n][m] (pointwise reads coalesced)
#pragma unroll
        for (int m = 0; m < 4; m++) {
#pragma unroll
            for (int nt = 0; nt < 2; nt++) {
                const int mrow = wm * 64 + m * 16 + gr;
                const int ncol = wn * 16 + nt * 8 + 2 * (lane & 3);
                pbase[(size_t)ncol * 128 + mrow]           = acc[m][nt][0];
                pbase[(size_t)(ncol + 1) * 128 + mrow]     = acc[m][nt][1];
                pbase[(size_t)ncol * 128 + mrow + 8]       = acc[m][nt][2];
                pbase[(size_t)(ncol + 1) * 128 + mrow + 8] = acc[m][nt][3];
            }
        }
        grid_sync();   // all partials visible

        // fused pointwise (c register-resident)
#pragma unroll
        for (int e = 0; e < 2; e++) {
            const int idx = e * 65536 + gthr, bb = idx >> 10, hc = idx & 1023;
            float gv[4];
#pragma unroll
            for (int g4 = 0; g4 < 4; g4++) {
                const int grow = g4 * 1024 + hc;
                const int mtg = grow >> 7, mr = grow & 127;
                float sum = bcr[e][g4];
#pragma unroll
                for (int kgi = 0; kgi < 4; kgi++)
                    sum += __ldcg(&g_part[((size_t)(kgi * 32 + mtg) << 14) + (size_t)bb * 128 + mr]);
                gv[g4] = sum;
            }
            const float ig = sigmoidf_(gv[0]), fg = sigmoidf_(gv[1]);
            const float gg = tanhf(gv[2]),     og = sigmoidf_(gv[3]);
            const float cv = fg * creg[e] + ig * gg;
            creg[e] = cv;
            const float hv = og * tanhf(cv);
            g_h[idx] = hv;
            out[(size_t)s * 131072 + idx] = hv;
            if (s == SEQ - 1) {
                out[(size_t)512 * 131072 + idx] = hv;            // hN
                out[(size_t)512 * 131072 + 131072 + idx] = cv;   // cN
            }
        }
        grid_sync();   // h(s+1) visible before next step's B loads
    }
}

extern "C" void kernel_launch(void* const* d_in, const int* in_sizes, int n_in,
                              void* d_out, int out_size)
{
    lstm_mma_kernel<<<NBLK, 512>>>((const float*)d_in[0], (const float*)d_in[1],
                                   (const float*)d_in[2], (const float*)d_in[3],
                                   (const float*)d_in[4], (float*)d_out);
}

// round 11
// speedup vs baseline: 4.0655x; 1.1652x over previous
#include <cuda_runtime.h>
#include <cuda_fp16.h>
#include <math.h>
#include <stdint.h>

#define SEQ 512
#define NBLK 128

// ---- device globals (no allocations allowed) ----
__device__ uint4 g_w[NBLK][32][8][32];        // A fragments, fp16 hi only: 16MB
__device__ uint2 g_xp[SEQ * 128 * 512];       // x pre-split: (hi half2, lo half2) per k-pair, 268MB
__device__ uint2 g_hp[128 * 512];             // h split pairs, rewritten per step
__device__ float g_part[4 * 32 * 128 * 128];  // split-K partials [kg*32+mt][n*128+m]
__device__ unsigned g_count = 0, g_gen = 0;

__device__ __forceinline__ void grid_sync() {
    __syncthreads();
    if (threadIdx.x == 0) {
        __threadfence();
        unsigned gen = g_gen;
        if (atomicAdd(&g_count, 1u) == NBLK - 1u) {
            g_count = 0; __threadfence(); atomicAdd(&g_gen, 1u);
        } else {
            while (*((volatile unsigned*)&g_gen) == gen) { }
            __threadfence();
        }
    }
    __syncthreads();
}

__device__ __forceinline__ float sigmoidf_(float v) { return 1.0f / (1.0f + expf(-v)); }

// float2 -> fp16 hi half2 + fp16 lo half2 (2-product split of activations)
__device__ __forceinline__ void split2(float2 f, uint32_t& h, uint32_t& l) {
    __half2 hh = __float22half2_rn(f);
    float2 hf = __half22float2(hh);
    __half2 hl = __float22half2_rn(make_float2(f.x - hf.x, f.y - hf.y));
    h = *(uint32_t*)&hh;
    l = *(uint32_t*)&hl;
}

#define MMA(c, a, b0, b1) \
    asm volatile("mma.sync.aligned.m16n8k16.row.col.f32.f16.f16.f32 " \
        "{%0,%1,%2,%3},{%4,%5,%6,%7},{%8,%9},{%0,%1,%2,%3};" \
        : "+f"((c)[0]), "+f"((c)[1]), "+f"((c)[2]), "+f"((c)[3]) \
        : "r"((a).x), "r"((a).y), "r"((a).z), "r"((a).w), "r"(b0), "r"(b1))

// Persistent kernel: 128 blocks x 512 threads.
// Block bid = (mt = bid>>2, kg = bid&3): gate rows [mt*128,+128) x 128 batch,
// K-slice [kg*512,+512) of fused K=2048 (x||h).
// Warp: wm = wid>>3 (64 gate rows), wn = wid&7 (16 batch cols).
__global__ void __launch_bounds__(512, 1)
lstm_mma_kernel(const float* __restrict__ x, const float* __restrict__ w_ih,
                const float* __restrict__ w_hh, const float* __restrict__ b_ih,
                const float* __restrict__ b_hh, float* __restrict__ out)
{
    const int tid  = threadIdx.x;
    const int lane = tid & 31, wid = tid >> 5;
    const int bid  = blockIdx.x, mt = bid >> 2, kg = bid & 3;
    const int wm   = wid >> 3, wn = wid & 7;
    const int gr   = lane >> 2, gc = (lane & 3) * 2;
    const int gthr = bid * 512 + tid;   // 0..65535

    // zero h pairs (deterministic replays; step-0 recurrent half reads zeros)
    g_hp[gthr * 2]     = make_uint2(0u, 0u);
    g_hp[gthr * 2 + 1] = make_uint2(0u, 0u);

    // ---- prologue 1: pack this block's W slice into fp16 fragments ----
    {
        const float* Wsrc = (kg < 2) ? (w_ih + kg * 512) : (w_hh + (kg - 2) * 512);
        for (int grp = wid; grp < 256; grp += 16) {
            const int ks = grp >> 3, mt8 = grp & 7;
            const int row = mt * 128 + mt8 * 16 + gr;
            const int col = ks * 16 + gc;
            const float* p0 = Wsrc + (size_t)row * 1024 + col;
            const float* p1 = Wsrc + (size_t)(row + 8) * 1024 + col;
            __half2 h0 = __float22half2_rn(*(const float2*)p0);        // (gr,   gc)
            __half2 h1 = __float22half2_rn(*(const float2*)p1);        // (gr+8, gc)
            __half2 h2 = __float22half2_rn(*(const float2*)(p0 + 8));  // (gr,   gc+8)
            __half2 h3 = __float22half2_rn(*(const float2*)(p1 + 8));  // (gr+8, gc+8)
            g_w[bid][ks][mt8][lane] = make_uint4(*(uint32_t*)&h0, *(uint32_t*)&h1,
                                                 *(uint32_t*)&h2, *(uint32_t*)&h3);
        }
    }

    // ---- prologue 2: pre-split ALL of x into (hi,lo) fp16 pairs ----
    {
        const int total8 = SEQ * 131072 / 8;   // 8 elems per iter
        for (int i = gthr; i < total8; i += 65536) {
            const float4 f0 = __ldg((const float4*)(x + (size_t)i * 8));
            const float4 f1 = __ldg((const float4*)(x + (size_t)i * 8 + 4));
            uint32_t h01, l01, h23, l23, h45, l45, h67, l67;
            split2(make_float2(f0.x, f0.y), h01, l01);
            split2(make_float2(f0.z, f0.w), h23, l23);
            split2(make_float2(f1.x, f1.y), h45, l45);
            split2(make_float2(f1.z, f1.w), h67, l67);
            *(uint4*)&g_xp[(size_t)i * 4]     = make_uint4(h01, l01, h23, l23);
            *(uint4*)&g_xp[(size_t)i * 4 + 2] = make_uint4(h45, l45, h67, l67);
        }
    }

    // pointwise constants (each thread owns 2 (b,h) elements)
    float bcr[2][4], creg[2] = {0.f, 0.f};
#pragma unroll
    for (int e = 0; e < 2; e++) {
        const int hc = (e * 65536 + gthr) & 1023;
#pragma unroll
        for (int g4 = 0; g4 < 4; g4++)
            bcr[e][g4] = b_ih[g4 * 1024 + hc] + b_hh[g4 * 1024 + hc];
    }
    grid_sync();   // g_w, g_xp, zeroed g_hp visible chip-wide

    const int  nB   = wn * 16 + gr;           // B batch row (+nt*8)
    const int  kq   = lane & 3;               // k-pair index within group of 4
    const int  aoffp = (kg & 1) * 256;        // k-pair base within 512-wide row
    const bool useh = (kg >= 2);
    float* pbase = g_part + ((size_t)(kg * 32 + mt) << 14);

    for (int s = 0; s < SEQ; s++) {
        const uint2* act = useh ? (g_hp + aoffp)
                                : (g_xp + (size_t)s * 65536 + aoffp);
        float acc[4][2][4];
#pragma unroll
        for (int m = 0; m < 4; m++)
#pragma unroll
            for (int nt = 0; nt < 2; nt++)
#pragma unroll
                for (int q = 0; q < 4; q++) acc[m][nt][q] = 0.f;

        // B prefetch ring, depth 2: v0 = k-pairs kq, v1 = kq+4 (k+8)
        uint2 v0[2][2], v1[2][2];
#pragma unroll
        for (int sl = 0; sl < 2; sl++)
#pragma unroll
            for (int nt = 0; nt < 2; nt++) {
                const uint2* ap = act + (size_t)(nB + nt * 8) * 512 + sl * 8 + kq;
                if (useh) { v0[sl][nt] = __ldcg(ap); v1[sl][nt] = __ldcg(ap + 4); }
                else      { v0[sl][nt] = __ldg(ap);  v1[sl][nt] = __ldg(ap + 4);  }
            }

#pragma unroll 2
        for (int ks = 0; ks < 32; ks++) {
            const int sl = ks & 1;
            uint2 c0[2], c1[2];
#pragma unroll
            for (int nt = 0; nt < 2; nt++) { c0[nt] = v0[sl][nt]; c1[nt] = v1[sl][nt]; }
            if (ks < 30) {
                const int kb = (ks + 2) * 8 + kq;
#pragma unroll
                for (int nt = 0; nt < 2; nt++) {
                    const uint2* ap = act + (size_t)(nB + nt * 8) * 512 + kb;
                    if (useh) { v0[sl][nt] = __ldcg(ap); v1[sl][nt] = __ldcg(ap + 4); }
                    else      { v0[sl][nt] = __ldg(ap);  v1[sl][nt] = __ldg(ap + 4);  }
                }
            }
#pragma unroll
            for (int m = 0; m < 4; m++) {
                const uint4 Ah = __ldg(&g_w[bid][ks][wm * 4 + m][lane]);
#pragma unroll
                for (int nt = 0; nt < 2; nt++) {
                    MMA(acc[m][nt], Ah, c0[nt].x, c1[nt].x);   // w_hi * a_hi
                    MMA(acc[m][nt], Ah, c0[nt].y, c1[nt].y);   // w_hi * a_lo
                }
            }
        }

        // write partials, layout [n][m] (pointwise reads coalesced)
#pragma unroll
        for (int m = 0; m < 4; m++) {
#pragma unroll
            for (int nt = 0; nt < 2; nt++) {
                const int mrow = wm * 64 + m * 16 + gr;
                const int ncol = wn * 16 + nt * 8 + 2 * (lane & 3);
                pbase[(size_t)ncol * 128 + mrow]           = acc[m][nt][0];
                pbase[(size_t)(ncol + 1) * 128 + mrow]     = acc[m][nt][1];
                pbase[(size_t)ncol * 128 + mrow + 8]       = acc[m][nt][2];
                pbase[(size_t)(ncol + 1) * 128 + mrow + 8] = acc[m][nt][3];
            }
        }
        grid_sync();   // all partials visible

        // fused pointwise (c register-resident); also write split h pairs
#pragma unroll
        for (int e = 0; e < 2; e++) {
            const int idx = e * 65536 + gthr, bb = idx >> 10, hc = idx & 1023;
            float gv[4];
#pragma unroll
            for (int g4 = 0; g4 < 4; g4++) {
                const int grow = g4 * 1024 + hc;
                const int mtg = grow >> 7, mr = grow & 127;
                float sum = bcr[e][g4];
#pragma unroll
                for (int kgi = 0; kgi < 4; kgi++)
                    sum += __ldcg(&g_part[((size_t)(kgi * 32 + mtg) << 14) + (size_t)bb * 128 + mr]);
                gv[g4] = sum;
            }
            const float ig = sigmoidf_(gv[0]), fg = sigmoidf_(gv[1]);
            const float gg = tanhf(gv[2]),     og = sigmoidf_(gv[3]);
            const float cv = fg * creg[e] + ig * gg;
            creg[e] = cv;
            const float hv = og * tanhf(cv);
            out[(size_t)s * 131072 + idx] = hv;
            if (s == SEQ - 1) {
                out[(size_t)512 * 131072 + idx] = hv;            // hN
                out[(size_t)512 * 131072 + 131072 + idx] = cv;   // cN
            }
            // pair with neighbor lane, split, store (even lanes)
            const float hvo = __shfl_xor_sync(0xffffffffu, hv, 1);
            if (!(lane & 1)) {
                uint32_t ph, pl;
                split2(make_float2(hv, hvo), ph, pl);
                g_hp[(size_t)bb * 512 + (hc >> 1)] = make_uint2(ph, pl);
            }
        }
        grid_sync();   // h(s+1) pairs visible before next step's B loads
    }
}

extern "C" void kernel_launch(void* const* d_in, const int* in_sizes, int n_in,
                              void* d_out, int out_size)
{
    lstm_mma_kernel<<<NBLK, 512>>>((const float*)d_in[0], (const float*)d_in[1],
                                   (const float*)d_in[2], (const float*)d_in[3],
                                   (const float*)d_in[4], (float*)d_out);
}

// round 16
// speedup vs baseline: 4.3512x; 1.0703x over previous
#include <cuda_runtime.h>
#include <cuda_fp16.h>
#include <stdint.h>

#define SEQ 512
#define NBLK 128

// ---- device globals (no allocations allowed) ----
__device__ uint4 g_wih[32][64][8][32];        // A fragments (fp16 hi), 8MB
__device__ uint4 g_whh[32][64][8][32];        // 8MB
__device__ uint4 g_xp[SEQ * 128 * 64 * 4];    // x pairs: [s][b][ks][kq] uint4(h0,l0,h8,l8), 268MB
__device__ uint4 g_hp[128 * 64 * 4];          // h pairs, same layout per b
__device__ float g_gx[(size_t)SEQ * 128 * 4096]; // gates_x + bias: [s][n][m], 1GB
__device__ float g_part[4 * 32 * 128 * 128];  // h-GEMM split-K partials [kg*32+mt][n][m]
__device__ unsigned g_count = 0, g_gen = 0;

__device__ __forceinline__ void grid_sync() {
    __syncthreads();
    if (threadIdx.x == 0) {
        __threadfence();
        unsigned gen = g_gen;
        if (atomicAdd(&g_count, 1u) == NBLK - 1u) {
            g_count = 0; __threadfence(); atomicAdd(&g_gen, 1u);
        } else {
            while (*((volatile unsigned*)&g_gen) == gen) { }
            __threadfence();
        }
    }
    __syncthreads();
}

__device__ __forceinline__ float fsig(float v) {
    float t, r;
    asm("ex2.approx.f32 %0, %1;" : "=f"(t) : "f"(-1.442695041f * v));
    asm("rcp.approx.f32 %0, %1;" : "=f"(r) : "f"(1.0f + t));
    return r;
}
__device__ __forceinline__ float ftanh(float v) {
    float t, r;
    asm("ex2.approx.f32 %0, %1;" : "=f"(t) : "f"(2.885390082f * v));
    asm("rcp.approx.f32 %0, %1;" : "=f"(r) : "f"(1.0f + t));
    return 1.0f - 2.0f * r;
}

// float2 -> fp16 hi half2 + lo half2 (2-product activation split)
__device__ __forceinline__ void split2(float2 f, uint32_t& h, uint32_t& l) {
    __half2 hh = __float22half2_rn(f);
    float2 hf = __half22float2(hh);
    __half2 hl = __float22half2_rn(make_float2(f.x - hf.x, f.y - hf.y));
    h = *(uint32_t*)&hh;
    l = *(uint32_t*)&hl;
}

#define MMA(c, a, b0, b1) \
    asm volatile("mma.sync.aligned.m16n8k16.row.col.f32.f16.f16.f32 " \
        "{%0,%1,%2,%3},{%4,%5,%6,%7},{%8,%9},{%0,%1,%2,%3};" \
        : "+f"((c)[0]), "+f"((c)[1]), "+f"((c)[2]), "+f"((c)[3]) \
        : "r"((a).x), "r"((a).y), "r"((a).z), "r"((a).w), "r"(b0), "r"(b1))

// pack one fragment group of W (row base, col base) -> uint4 per lane
__device__ __forceinline__ uint4 pack_w(const float* W, int row, int col) {
    const float* p0 = W + (size_t)row * 1024 + col;
    const float* p1 = W + (size_t)(row + 8) * 1024 + col;
    __half2 h0 = __float22half2_rn(*(const float2*)p0);
    __half2 h1 = __float22half2_rn(*(const float2*)p1);
    __half2 h2 = __float22half2_rn(*(const float2*)(p0 + 8));
    __half2 h3 = __float22half2_rn(*(const float2*)(p1 + 8));
    return make_uint4(*(uint32_t*)&h0, *(uint32_t*)&h1, *(uint32_t*)&h2, *(uint32_t*)&h3);
}

// ============================================================================
// Phase A: prologue packing + gates_x GEMM (no recurrence, one grid_sync)
// Block bid = (mt = bid>>2, sq = bid&3). Warp: wm = wid>>3 (64 rows), wn = wid&7.
// ============================================================================
__global__ void __launch_bounds__(512, 1)
lstm_phaseA(const float* __restrict__ x, const float* __restrict__ w_ih,
            const float* __restrict__ w_hh, const float* __restrict__ b_ih,
            const float* __restrict__ b_hh)
{
    const int tid = threadIdx.x, lane = tid & 31, wid = tid >> 5;
    const int bid = blockIdx.x, mt = bid >> 2, sq = bid & 3;
    const int wm = wid >> 3, wn = wid & 7;
    const int gr = lane >> 2, gc = (lane & 3) * 2;
    const int gthr = bid * 512 + tid;

    // ---- pack weights (both matrices) ----
    const int wg = bid * 16 + wid;   // 2048 warps
    for (int g = wg; g < 16384; g += 2048) {
        const int pmt = g >> 9, pks = (g >> 3) & 63, pm8 = g & 7;
        const int row = pmt * 128 + pm8 * 16 + gr, col = pks * 16 + gc;
        g_wih[pmt][pks][pm8][lane] = pack_w(w_ih, row, col);
        g_whh[pmt][pks][pm8][lane] = pack_w(w_hh, row, col);
    }

    // ---- pre-split x into fragment-native uint4 pairs ----
    for (int id = gthr; id < SEQ * 128 * 64; id += 65536) {
        float e[16];
        *(float4*)&e[0]  = __ldg((const float4*)(x + (size_t)id * 16));
        *(float4*)&e[4]  = __ldg((const float4*)(x + (size_t)id * 16 + 4));
        *(float4*)&e[8]  = __ldg((const float4*)(x + (size_t)id * 16 + 8));
        *(float4*)&e[12] = __ldg((const float4*)(x + (size_t)id * 16 + 12));
#pragma unroll
        for (int kq = 0; kq < 4; kq++) {
            uint32_t h0, l0, h8, l8;
            split2(make_float2(e[2 * kq], e[2 * kq + 1]), h0, l0);
            split2(make_float2(e[2 * kq + 8], e[2 * kq + 9]), h8, l8);
            g_xp[(size_t)id * 4 + kq] = make_uint4(h0, l0, h8, l8);
        }
    }

    // ---- zero h pairs ----
    if (gthr < 32768) g_hp[gthr] = make_uint4(0u, 0u, 0u, 0u);

    // combined biases for this warp's rows (hoisted across all s)
    float brow[4][2];
#pragma unroll
    for (int m = 0; m < 4; m++) {
        const int r0 = mt * 128 + wm * 64 + m * 16 + gr;
        brow[m][0] = b_ih[r0] + b_hh[r0];
        brow[m][1] = b_ih[r0 + 8] + b_hh[r0 + 8];
    }

    grid_sync();   // packed data visible chip-wide

    // ---- gates_x GEMM: tile 128m x 128n, K=1024, per block 128 s-values ----
    const int nB = wn * 16 + gr;
    const int kq = lane & 3;

    for (int si = 0; si < 128; si++) {
        const int s = sq * 128 + si;
        const uint4* act = g_xp + (size_t)s * 128 * 256;   // [b][ks][kq]

        float acc[4][2][4];
#pragma unroll
        for (int m = 0; m < 4; m++)
#pragma unroll
            for (int nt = 0; nt < 2; nt++)
#pragma unroll
                for (int q = 0; q < 4; q++) acc[m][nt][q] = 0.f;

        uint4 v[2][2];
#pragma unroll
        for (int d = 0; d < 2; d++)
#pragma unroll
            for (int nt = 0; nt < 2; nt++)
                v[d][nt] = __ldg(act + ((size_t)(nB + nt * 8) * 64 + d) * 4 + kq);

#pragma unroll 2
        for (int ks = 0; ks < 64; ks++) {
            const int sl = ks & 1;
            uint4 cur[2];
            cur[0] = v[sl][0]; cur[1] = v[sl][1];
            if (ks < 62) {
#pragma unroll
                for (int nt = 0; nt < 2; nt++)
                    v[sl][nt] = __ldg(act + ((size_t)(nB + nt * 8) * 64 + ks + 2) * 4 + kq);
            }
#pragma unroll
            for (int m = 0; m < 4; m++) {
                const uint4 Ah = __ldg(&g_wih[mt][ks][wm * 4 + m][lane]);
#pragma unroll
                for (int nt = 0; nt < 2; nt++) {
                    MMA(acc[m][nt], Ah, cur[nt].x, cur[nt].z);   // w * a_hi
                    MMA(acc[m][nt], Ah, cur[nt].y, cur[nt].w);   // w * a_lo
                }
            }
        }

        // epilogue: add bias, write gx[s][n][m]
        float* gx = g_gx + (size_t)s * 128 * 4096 + mt * 128;
#pragma unroll
        for (int m = 0; m < 4; m++) {
#pragma unroll
            for (int nt = 0; nt < 2; nt++) {
                const int mrow = wm * 64 + m * 16 + gr;
                const int ncol = wn * 16 + nt * 8 + 2 * (lane & 3);
                gx[(size_t)ncol * 4096 + mrow]           = acc[m][nt][0] + brow[m][0];
                gx[(size_t)(ncol + 1) * 4096 + mrow]     = acc[m][nt][1] + brow[m][0];
                gx[(size_t)ncol * 4096 + mrow + 8]       = acc[m][nt][2] + brow[m][1];
                gx[(size_t)(ncol + 1) * 4096 + mrow + 8] = acc[m][nt][3] + brow[m][1];
            }
        }
    }
}

// ============================================================================
// Phase B: recurrence. Block bid = (mt = bid>>2, kg = bid&3).
// h-GEMM per step: gate rows [mt*128,+128) x 128 batch, K-slice [kg*256,+256).
// Warp geometry m128 x n8: wn = wid (16 n8-tiles), no B duplication.
// ============================================================================
__global__ void __launch_bounds__(512, 1)
lstm_phaseB(float* __restrict__ out)
{
    const int tid = threadIdx.x, lane = tid & 31, wid = tid >> 5;
    const int bid = blockIdx.x, mt = bid >> 2, kg = bid & 3;
    const int gr = lane >> 2, kq = lane & 3;
    const int gthr = bid * 512 + tid;
    const int nB = wid * 8 + gr;                 // this warp's n8 rows
    float* pbase = g_part + ((size_t)(kg * 32 + mt) << 14);
    float creg[2] = {0.f, 0.f};

    for (int s = 0; s < SEQ; s++) {
        float acc[8][4];
#pragma unroll
        for (int m = 0; m < 8; m++)
#pragma unroll
            for (int q = 0; q < 4; q++) acc[m][q] = 0.f;

        const uint4* act = g_hp + ((size_t)nB * 64 + kg * 16) * 4 + kq;
        uint4 v0 = __ldcg(act);
        uint4 v1 = __ldcg(act + 4);

#pragma unroll 2
        for (int ks = 0; ks < 16; ks++) {
            uint4 cur = (ks & 1) ? v1 : v0;
            if (ks < 14) {
                uint4 nv = __ldcg(act + (ks + 2) * 4);
                if (ks & 1) v1 = nv; else v0 = nv;
            }
#pragma unroll
            for (int m = 0; m < 8; m++) {
                const uint4 Ah = __ldg(&g_whh[mt][kg * 16 + ks][m][lane]);
                MMA(acc[m], Ah, cur.x, cur.z);   // w * h_hi
                MMA(acc[m], Ah, cur.y, cur.w);   // w * h_lo
            }
        }

        // write partials [n][m]
        const int ncol = wid * 8 + 2 * kq;
#pragma unroll
        for (int m = 0; m < 8; m++) {
            const int mrow = m * 16 + gr;
            pbase[(size_t)ncol * 128 + mrow]           = acc[m][0];
            pbase[(size_t)(ncol + 1) * 128 + mrow]     = acc[m][1];
            pbase[(size_t)ncol * 128 + mrow + 8]       = acc[m][2];
            pbase[(size_t)(ncol + 1) * 128 + mrow + 8] = acc[m][3];
        }
        grid_sync();   // partials visible

        // fused pointwise (c register-resident), 2 (b,h) elements per thread
        float hv2[2];
#pragma unroll
        for (int e = 0; e < 2; e++) {
            const int idx = e * 65536 + gthr, bb = idx >> 10, hc = idx & 1023;
            const float* gxr = g_gx + (size_t)s * 128 * 4096 + (size_t)bb * 4096;
            float gv[4];
#pragma unroll
            for (int g4 = 0; g4 < 4; g4++) {
                const int grow = g4 * 1024 + hc;
                const int mtg = grow >> 7, mr = grow & 127;
                float sum = __ldg(gxr + grow);   // includes biases
#pragma unroll
                for (int kgi = 0; kgi < 4; kgi++)
                    sum += __ldcg(&g_part[((size_t)(kgi * 32 + mtg) << 14) + (size_t)bb * 128 + mr]);
                gv[g4] = sum;
            }
            const float ig = fsig(gv[0]), fg = fsig(gv[1]);
            const float gg = ftanh(gv[2]), og = fsig(gv[3]);
            const float cv = fg * creg[e] + ig * gg;
            creg[e] = cv;
            const float hv = og * ftanh(cv);
            hv2[e] = hv;
            out[(size_t)s * 131072 + idx] = hv;
            if (s == SEQ - 1) {
                out[(size_t)512 * 131072 + idx] = hv;            // hN
                out[(size_t)512 * 131072 + 131072 + idx] = cv;   // cN
            }
        }
        // write h pairs in fragment-native layout (writers: lane%16 < 4)
#pragma unroll
        for (int e = 0; e < 2; e++) {
            const int idx = e * 65536 + gthr, bb = idx >> 10, hc = idx & 1023;
            const float hv = hv2[e];
            const int lb = lane & 16;
            const float a0 = __shfl_sync(0xffffffffu, hv, lb + 2 * kq,     32);
            const float a1 = __shfl_sync(0xffffffffu, hv, lb + 2 * kq + 1, 32);
            const float a2 = __shfl_sync(0xffffffffu, hv, lb + 2 * kq + 8, 32);
            const float a3 = __shfl_sync(0xffffffffu, hv, lb + 2 * kq + 9, 32);
            if ((lane & 15) < 4) {
                uint32_t h0, l0, h8, l8;
                split2(make_float2(a0, a1), h0, l0);
                split2(make_float2(a2, a3), h8, l8);
                g_hp[((size_t)bb * 64 + (hc >> 4)) * 4 + kq] = make_uint4(h0, l0, h8, l8);
            }
        }
        grid_sync();   // h(s+1) visible
    }
}

extern "C" void kernel_launch(void* const* d_in, const int* in_sizes, int n_in,
                              void* d_out, int out_size)
{
    const float* x    = (const float*)d_in[0];
    const float* w_ih = (const float*)d_in[1];
    const float* w_hh = (const float*)d_in[2];
    const float* b_ih = (const float*)d_in[3];
    const float* b_hh = (const float*)d_in[4];

    lstm_phaseA<<<NBLK, 512>>>(x, w_ih, w_hh, b_ih, b_hh);
    lstm_phaseB<<<NBLK, 512>>>((float*)d_out);
}

// round 17
// speedup vs baseline: 4.7410x; 1.0896x over previous
#include <cuda_runtime.h>
#include <cuda_fp16.h>
#include <stdint.h>

#define SEQ 512
#define NBLK 128

// ---- device globals (no allocations allowed) ----
// Weight fragments in PERMUTED row order: p = hcol*4 + gate
__device__ uint4 g_wih2[32][64][8][32];          // 8MB
__device__ uint4 g_whh2[32][64][8][32];          // 8MB
__device__ uint4 g_xp[SEQ * 128 * 64 * 4];       // x pairs [s][b][ks][kq], 268MB
__device__ uint4 g_hp[2][128 * 64 * 4];          // h pairs, double-buffered
__device__ float g_gx[(size_t)SEQ * 128 * 4096]; // gates_x+bias, PERMUTED m: [s][b][4*hcol+g]
__device__ unsigned g_count = 0, g_gen = 0;

__device__ __forceinline__ void grid_sync() {
    __syncthreads();
    if (threadIdx.x == 0) {
        __threadfence();
        unsigned gen = g_gen;
        if (atomicAdd(&g_count, 1u) == NBLK - 1u) {
            g_count = 0; __threadfence(); atomicAdd(&g_gen, 1u);
        } else {
            while (*((volatile unsigned*)&g_gen) == gen) { }
            __threadfence();
        }
    }
    __syncthreads();
}

__device__ __forceinline__ float fsig(float v) {
    float t, r;
    asm("ex2.approx.f32 %0, %1;" : "=f"(t) : "f"(-1.442695041f * v));
    asm("rcp.approx.f32 %0, %1;" : "=f"(r) : "f"(1.0f + t));
    return r;
}
__device__ __forceinline__ float ftanh(float v) {
    float t, r;
    asm("ex2.approx.f32 %0, %1;" : "=f"(t) : "f"(2.885390082f * v));
    asm("rcp.approx.f32 %0, %1;" : "=f"(r) : "f"(1.0f + t));
    return 1.0f - 2.0f * r;
}

__device__ __forceinline__ void split2(float2 f, uint32_t& h, uint32_t& l) {
    __half2 hh = __float22half2_rn(f);
    float2 hf = __half22float2(hh);
    __half2 hl = __float22half2_rn(make_float2(f.x - hf.x, f.y - hf.y));
    h = *(uint32_t*)&hh;
    l = *(uint32_t*)&hl;
}

#define MMA(c, a, b0, b1) \
    asm volatile("mma.sync.aligned.m16n8k16.row.col.f32.f16.f16.f32 " \
        "{%0,%1,%2,%3},{%4,%5,%6,%7},{%8,%9},{%0,%1,%2,%3};" \
        : "+f"((c)[0]), "+f"((c)[1]), "+f"((c)[2]), "+f"((c)[3]) \
        : "r"((a).x), "r"((a).y), "r"((a).z), "r"((a).w), "r"(b0), "r"(b1))

// permuted index p -> original W row (gate = p&3, hcol = p>>2)
__device__ __forceinline__ int permrow(int p) { return (p & 3) * 1024 + (p >> 2); }

// pack fragment: permuted rows p, p+8 (global rows r0, r0+2), cols col..col+9
__device__ __forceinline__ uint4 pack_w2(const float* W, int p, int col) {
    const int r0 = permrow(p), r1 = permrow(p + 8);
    const float* p0 = W + (size_t)r0 * 1024 + col;
    const float* p1 = W + (size_t)r1 * 1024 + col;
    __half2 h0 = __float22half2_rn(*(const float2*)p0);
    __half2 h1 = __float22half2_rn(*(const float2*)p1);
    __half2 h2 = __float22half2_rn(*(const float2*)(p0 + 8));
    __half2 h3 = __float22half2_rn(*(const float2*)(p1 + 8));
    return make_uint4(*(uint32_t*)&h0, *(uint32_t*)&h1, *(uint32_t*)&h2, *(uint32_t*)&h3);
}

// ============================================================================
// Phase A: pack weights (permuted), pre-split x, zero h, gates_x GEMM
// ============================================================================
__global__ void __launch_bounds__(512, 1)
lstm_phaseA(const float* __restrict__ x, const float* __restrict__ w_ih,
            const float* __restrict__ w_hh, const float* __restrict__ b_ih,
            const float* __restrict__ b_hh)
{
    const int tid = threadIdx.x, lane = tid & 31, wid = tid >> 5;
    const int bid = blockIdx.x, mt = bid >> 2, sq = bid & 3;
    const int wm = wid >> 3, wn = wid & 7;
    const int gr = lane >> 2, gc = (lane & 3) * 2;
    const int gthr = bid * 512 + tid;

    // pack both weight matrices (permuted rows)
    const int wg = bid * 16 + wid;
    for (int g = wg; g < 16384; g += 2048) {
        const int pmt = g >> 9, pks = (g >> 3) & 63, pm8 = g & 7;
        const int p = pmt * 128 + pm8 * 16 + gr, col = pks * 16 + gc;
        g_wih2[pmt][pks][pm8][lane] = pack_w2(w_ih, p, col);
        g_whh2[pmt][pks][pm8][lane] = pack_w2(w_hh, p, col);
    }

    // pre-split x into fragment-native uint4 pairs
    for (int id = gthr; id < SEQ * 128 * 64; id += 65536) {
        float e[16];
        *(float4*)&e[0]  = __ldg((const float4*)(x + (size_t)id * 16));
        *(float4*)&e[4]  = __ldg((const float4*)(x + (size_t)id * 16 + 4));
        *(float4*)&e[8]  = __ldg((const float4*)(x + (size_t)id * 16 + 8));
        *(float4*)&e[12] = __ldg((const float4*)(x + (size_t)id * 16 + 12));
#pragma unroll
        for (int kq = 0; kq < 4; kq++) {
            uint32_t h0, l0, h8, l8;
            split2(make_float2(e[2 * kq], e[2 * kq + 1]), h0, l0);
            split2(make_float2(e[2 * kq + 8], e[2 * kq + 9]), h8, l8);
            g_xp[(size_t)id * 4 + kq] = make_uint4(h0, l0, h8, l8);
        }
    }

    // zero h pairs (buffer 0)
    if (gthr < 32768) g_hp[0][gthr] = make_uint4(0u, 0u, 0u, 0u);

    // combined biases for this warp's PERMUTED rows
    float brow[4][2];
#pragma unroll
    for (int m = 0; m < 4; m++) {
        const int p0 = mt * 128 + wm * 64 + m * 16 + gr;
        const int r0 = permrow(p0), r1 = permrow(p0 + 8);
        brow[m][0] = b_ih[r0] + b_hh[r0];
        brow[m][1] = b_ih[r1] + b_hh[r1];
    }

    grid_sync();

    // gates_x GEMM: tile 128m(perm) x 128n, K=1024; block covers 128 s-values
    const int nB = wn * 16 + gr;
    const int kq = lane & 3;

    for (int si = 0; si < 128; si++) {
        const int s = sq * 128 + si;
        const uint4* act = g_xp + (size_t)s * 128 * 256;

        float acc[4][2][4];
#pragma unroll
        for (int m = 0; m < 4; m++)
#pragma unroll
            for (int nt = 0; nt < 2; nt++)
#pragma unroll
                for (int q = 0; q < 4; q++) acc[m][nt][q] = 0.f;

        uint4 v[2][2];
#pragma unroll
        for (int d = 0; d < 2; d++)
#pragma unroll
            for (int nt = 0; nt < 2; nt++)
                v[d][nt] = __ldg(act + ((size_t)(nB + nt * 8) * 64 + d) * 4 + kq);

#pragma unroll 2
        for (int ks = 0; ks < 64; ks++) {
            const int sl = ks & 1;
            uint4 cur[2];
            cur[0] = v[sl][0]; cur[1] = v[sl][1];
            if (ks < 62) {
#pragma unroll
                for (int nt = 0; nt < 2; nt++)
                    v[sl][nt] = __ldg(act + ((size_t)(nB + nt * 8) * 64 + ks + 2) * 4 + kq);
            }
#pragma unroll
            for (int m = 0; m < 4; m++) {
                const uint4 Ah = __ldg(&g_wih2[mt][ks][wm * 4 + m][lane]);
#pragma unroll
                for (int nt = 0; nt < 2; nt++) {
                    MMA(acc[m][nt], Ah, cur[nt].x, cur[nt].z);
                    MMA(acc[m][nt], Ah, cur[nt].y, cur[nt].w);
                }
            }
        }

        float* gx = g_gx + (size_t)s * 128 * 4096 + mt * 128;
#pragma unroll
        for (int m = 0; m < 4; m++) {
#pragma unroll
            for (int nt = 0; nt < 2; nt++) {
                const int mrow = wm * 64 + m * 16 + gr;
                const int ncol = wn * 16 + nt * 8 + 2 * (lane & 3);
                gx[(size_t)ncol * 4096 + mrow]           = acc[m][nt][0] + brow[m][0];
                gx[(size_t)(ncol + 1) * 4096 + mrow]     = acc[m][nt][1] + brow[m][0];
                gx[(size_t)ncol * 4096 + mrow + 8]       = acc[m][nt][2] + brow[m][1];
                gx[(size_t)(ncol + 1) * 4096 + mrow + 8] = acc[m][nt][3] + brow[m][1];
            }
        }
    }
}

// ============================================================================
// Phase B: recurrence, ONE grid sync per step.
// Block (hb = bid>>2, nq = bid&3): permuted gate rows [hb*128,+128) (= all 4
// gates of h-cols [hb*32,+32)) x batch [nq*32,+32), full K=1024.
// Warp (wm = wid>>2, wn = wid&3): tile m32 x n8. Gates exchanged via SMEM.
// ============================================================================
__global__ void __launch_bounds__(512, 1)
lstm_phaseB(float* __restrict__ out)
{
    __shared__ float gsm[128][33];
    const int tid = threadIdx.x, lane = tid & 31, wid = tid >> 5;
    const int bid = blockIdx.x, hb = bid >> 2, nq = bid & 3;
    const int wm = wid >> 2, wn = wid & 3;
    const int gr = lane >> 2, kq = lane & 3;
    const int nB = nq * 32 + wn * 8 + gr;       // batch row for B fragments
    float creg[2] = {0.f, 0.f};

    for (int s = 0; s < SEQ; s++) {
        // prefetch gx (includes biases) for this thread's 2 (b,h) elements
        float4 gxv[2];
#pragma unroll
        for (int e = 0; e < 2; e++) {
            const int b = nq * 32 + e * 16 + wid;
            const int hcol = hb * 32 + lane;
            gxv[e] = __ldcg((const float4*)(g_gx + (size_t)s * 524288 + (size_t)b * 4096 + hcol * 4));
        }

        // h-GEMM: m32 x n8 x K=1024 per warp
        float acc[2][4];
#pragma unroll
        for (int m = 0; m < 2; m++)
#pragma unroll
            for (int q = 0; q < 4; q++) acc[m][q] = 0.f;

        const uint4* actb = g_hp[s & 1] + (size_t)nB * 256 + kq;
        uint4 v0 = __ldcg(actb);
        uint4 v1 = __ldcg(actb + 4);

#pragma unroll 4
        for (int ks = 0; ks < 64; ks++) {
            uint4 cur = (ks & 1) ? v1 : v0;
            if (ks < 62) {
                uint4 nv = __ldcg(actb + (ks + 2) * 4);
                if (ks & 1) v1 = nv; else v0 = nv;
            }
            const uint4 A0 = __ldg(&g_whh2[hb][ks][wm * 2][lane]);
            const uint4 A1 = __ldg(&g_whh2[hb][ks][wm * 2 + 1][lane]);
            MMA(acc[0], A0, cur.x, cur.z);
            MMA(acc[0], A0, cur.y, cur.w);
            MMA(acc[1], A1, cur.x, cur.z);
            MMA(acc[1], A1, cur.y, cur.w);
        }

        // gates -> SMEM (block-local exchange)
#pragma unroll
        for (int m = 0; m < 2; m++) {
            const int mrow = wm * 32 + m * 16 + gr;
            const int ncol = wn * 8 + 2 * kq;
            gsm[mrow][ncol]         = acc[m][0];
            gsm[mrow][ncol + 1]     = acc[m][1];
            gsm[mrow + 8][ncol]     = acc[m][2];
            gsm[mrow + 8][ncol + 1] = acc[m][3];
        }
        __syncthreads();

        // fused pointwise: warp w handles batch rows e*16+w, h-cols = lane
#pragma unroll
        for (int e = 0; e < 2; e++) {
            const int bb = e * 16 + wid;              // 0..31 local batch
            const int b  = nq * 32 + bb;
            const int hc = lane;                      // local h-col
            const int hcol = hb * 32 + hc;
            const float gi = gxv[e].x + gsm[4 * hc + 0][bb];
            const float gf = gxv[e].y + gsm[4 * hc + 1][bb];
            const float gg = gxv[e].z + gsm[4 * hc + 2][bb];
            const float go = gxv[e].w + gsm[4 * hc + 3][bb];
            const float ig = fsig(gi), fg = fsig(gf);
            const float gv = ftanh(gg), og = fsig(go);
            const float cv = fg * creg[e] + ig * gv;
            creg[e] = cv;
            const float hv = og * ftanh(cv);
            const int idx = b * 1024 + hcol;
            out[(size_t)s * 131072 + idx] = hv;
            if (s == SEQ - 1) {
                out[(size_t)512 * 131072 + idx] = hv;            // hN
                out[(size_t)512 * 131072 + 131072 + idx] = cv;   // cN
            }
            // h fragment write (lanes with (lane&15)<4 write one uint4)
            const int lb = lane & 16;
            const float a0 = __shfl_sync(0xffffffffu, hv, lb + 2 * kq,     32);
            const float a1 = __shfl_sync(0xffffffffu, hv, lb + 2 * kq + 1, 32);
            const float a2 = __shfl_sync(0xffffffffu, hv, lb + 2 * kq + 8, 32);
            const float a3 = __shfl_sync(0xffffffffu, hv, lb + 2 * kq + 9, 32);
            if ((lane & 15) < 4) {
                uint32_t h0, l0, h8, l8;
                split2(make_float2(a0, a1), h0, l0);
                split2(make_float2(a2, a3), h8, l8);
                const int ksg = hb * 2 + (lane >> 4);
                g_hp[(s + 1) & 1][((size_t)b * 64 + ksg) * 4 + kq] = make_uint4(h0, l0, h8, l8);
            }
        }
        grid_sync();   // h(s+1) + SMEM reuse safe
    }
}

extern "C" void kernel_launch(void* const* d_in, const int* in_sizes, int n_in,
                              void* d_out, int out_size)
{
    const float* x    = (const float*)d_in[0];
    const float* w_ih = (const float*)d_in[1];
    const float* w_hh = (const float*)d_in[2];
    const float* b_ih = (const float*)d_in[3];
    const float* b_hh = (const float*)d_in[4];

    lstm_phaseA<<<NBLK, 512>>>(x, w_ih, w_hh, b_ih, b_hh);
    lstm_phaseB<<<NBLK, 512>>>((float*)d_out);
}